// round 8
// baseline (speedup 1.0000x reference)
#include <cuda_runtime.h>
#include <cuda_bf16.h>

// LightplaneSplatter: splat N rays x 72 samples x 16 channels into a
// (1,128,128,128,16) grid with trilinear weights, masking OOB corners.
//
// R7: per-ray (per-block) corner-vertex deduplication. Since the encoding e
// is constant per ray, each corner voxel's contribution is (sum of trilinear
// weights) * e. Phase 1 accumulates scalar weights into an smem hash table
// keyed by corner (ix,iy,iz); phase 2 flushes one 64B red.global.add.v4 group
// per distinct corner. Adjacent cells share 4/8 corners -> ~3x fewer atomics.
//
// Inputs (metadata order):
//   d_in[0] directions  float32 [N,3]
//   d_in[1] origins     float32 [N,3]
//   d_in[2] near        float32 [N]
//   d_in[3] far         float32 [N]
//   d_in[4] encoding    float32 [N,16]
//   d_in[5] grid_idx    int32   [N]
// Output: float32 grid [1,128,128,128,16] flattened (33,554,432 elems).

#define GW 128
#define GH 128
#define GD 128
#define GC 16
#define NUM_SAMPLES 64
#define NUM_SAMPLES_INF 8
#define ST (NUM_SAMPLES + NUM_SAMPLES_INF)  // 72
#define DISPARITY_AT_INF 1e-4f

#define NTHREADS 288        // 4 threads per sample x 72 samples
#define TBL 1024            // hash slots (>= 576 worst-case distinct corners)

__device__ __forceinline__ void red_add_v4(float* p, float x, float y, float z, float w) {
    asm volatile("red.global.add.v4.f32 [%0], {%1, %2, %3, %4};"
                 :: "l"(p), "f"(x), "f"(y), "f"(z), "f"(w)
                 : "memory");
}

__global__ void __launch_bounds__(NTHREADS) splat_kernel(
    const float* __restrict__ dirs,
    const float* __restrict__ orig,
    const float* __restrict__ nearv,
    const float* __restrict__ farv,
    const float* __restrict__ enc,
    const int*   __restrict__ gidx,
    float* __restrict__ out)
{
    __shared__ int   hkey[TBL];
    __shared__ float hval[TBL];

    const int n   = blockIdx.x;
    const int tid = threadIdx.x;
    const int si  = tid >> 2;   // 0..71 sample
    const int sub = tid & 3;    // 0..3  (2 corners each)

    // ---- init hash table ----
#pragma unroll
    for (int i = tid; i < TBL; i += NTHREADS) {
        hkey[i] = -1;
        hval[i] = 0.0f;
    }
    __syncthreads();

    // ---- phase 1: geometry + corner-weight accumulation ----
    {
        const float nr = nearv[n];
        const float fr = farv[n];

        float t;
        if (si < NUM_SAMPLES) {
            t = nr + (fr - nr) * (((float)si + 0.5f) * (1.0f / NUM_SAMPLES));
        } else {
            const float j    = (float)(si - NUM_SAMPLES + 1) * (1.0f / NUM_SAMPLES_INF);
            const float invf = 1.0f / fr;
            const float disp = invf + (DISPARITY_AT_INF - invf) * j;
            t = 1.0f / disp;
        }

        const float px = orig[n * 3 + 0] + t * dirs[n * 3 + 0];
        const float py = orig[n * 3 + 1] + t * dirs[n * 3 + 1];
        const float pz = orig[n * 3 + 2] + t * dirs[n * 3 + 2];

        const float vx = (px + 1.0f) * 0.5f * (float)(GW - 1);
        const float vy = (py + 1.0f) * 0.5f * (float)(GH - 1);
        const float vz = (pz + 1.0f) * 0.5f * (float)(GD - 1);

        const float bxf = floorf(vx);
        const float byf = floorf(vy);
        const float bzf = floorf(vz);

        // Written so NaN also fails -> skip.
        const bool maybe_in =
            (bxf >= -1.0f) && (bxf <= (float)(GW - 1)) &&
            (byf >= -1.0f) && (byf <= (float)(GH - 1)) &&
            (bzf >= -1.0f) && (bzf <= (float)(GD - 1));

        if (maybe_in) {
            const float fx = vx - bxf;
            const float fy = vy - byf;
            const float fz = vz - bzf;
            const int bx = (int)bxf;
            const int by = (int)byf;
            const int bz = (int)bzf;

            const float wx[2] = {1.0f - fx, fx};
            const float wy[2] = {1.0f - fy, fy};
            const float wz[2] = {1.0f - fz, fz};

#pragma unroll
            for (int kk = 0; kk < 2; kk++) {
                const int k  = sub * 2 + kk;
                const int dx = k & 1, dy = (k >> 1) & 1, dz = (k >> 2) & 1;
                const int ix = bx + dx;
                const int iy = by + dy;
                const int iz = bz + dz;
                if ((unsigned)ix < GW && (unsigned)iy < GH && (unsigned)iz < GD) {
                    const float w = wx[dx] * wy[dy] * wz[dz];
                    const int key = (iz << 14) | (iy << 7) | ix;
                    unsigned slot = ((unsigned)key * 2654435761u) & (TBL - 1);
                    for (;;) {
                        const int prev = atomicCAS(&hkey[slot], -1, key);
                        if (prev == -1 || prev == key) {
                            atomicAdd(&hval[slot], w);
                            break;
                        }
                        slot = (slot + 1) & (TBL - 1);
                    }
                }
            }
        }
    }
    __syncthreads();

    // ---- phase 2: flush distinct corners ----
    const int b = gidx[n];
    const int c4 = tid & 3;                 // channel quad
    const int g  = tid >> 2;                // flush group (0..71)
    const float4 e = *reinterpret_cast<const float4*>(enc + n * GC + c4 * 4);

    for (int slot = g; slot < TBL; slot += (NTHREADS / 4)) {
        const int key = hkey[slot];         // broadcast within quad
        if (key >= 0) {
            const float w = hval[slot];
            const int ix = key & 127;
            const int iy = (key >> 7) & 127;
            const int iz = key >> 14;
            const long long flat =
                ((((long long)b * GD + iz) * GH + iy) * GW + ix) * GC + c4 * 4;
            red_add_v4(out + flat, w * e.x, w * e.y, w * e.z, w * e.w);
        }
    }
}

extern "C" void kernel_launch(void* const* d_in, const int* in_sizes, int n_in,
                              void* d_out, int out_size)
{
    const float* dirs  = (const float*)d_in[0];
    const float* orig  = (const float*)d_in[1];
    const float* nearv = (const float*)d_in[2];
    const float* farv  = (const float*)d_in[3];
    const float* enc   = (const float*)d_in[4];
    const int*   gidx  = (const int*)  d_in[5];
    float* out = (float*)d_out;

    const int N = in_sizes[2];  // near has one element per ray

    cudaMemsetAsync(d_out, 0, (size_t)out_size * sizeof(float));

    splat_kernel<<<N, NTHREADS>>>(dirs, orig, nearv, farv, enc, gidx, out);
}

// round 9
// speedup vs baseline: 1.5214x; 1.5214x over previous
#include <cuda_runtime.h>
#include <cuda_bf16.h>

// LightplaneSplatter: splat N rays x 72 samples x 16 channels into a
// (1,128,128,128,16) grid with trilinear weights, masking OOB corners.
//
// R8: conflict-free corner-vertex dedup by dominant-axis slabs.
// Block = 1 ray, 128 threads. Thread M owns all corner vertices whose
// dominant-axis coordinate equals M. Cross-axis coords of those vertices
// provably fit a 4x4 window around the ray line (slope <= 1), so each
// thread accumulates into its private 16-slot smem column with plain
// load/add/store (no atomics). Then nonzero slots are compacted and
// flushed as 64B red.global.add.v4 quads (one wavefront per vertex).
//
// Inputs (metadata order):
//   d_in[0] directions  float32 [N,3]
//   d_in[1] origins     float32 [N,3]
//   d_in[2] near        float32 [N]
//   d_in[3] far         float32 [N]
//   d_in[4] encoding    float32 [N,16]
//   d_in[5] grid_idx    int32   [N]
// Output: float32 grid [1,128,128,128,16] flattened (33,554,432 elems).

#define GW 128
#define GH 128
#define GD 128
#define GC 16
#define NUM_SAMPLES 64
#define NUM_SAMPLES_INF 8
#define DISPARITY_AT_INF 1e-4f

#define NT 128      // threads per block = dominant-axis slabs
#define NSLOT 16    // 4x4 cross-axis window per slab

__device__ __forceinline__ void red_add_v4(float* p, float x, float y, float z, float w) {
    asm volatile("red.global.add.v4.f32 [%0], {%1, %2, %3, %4};"
                 :: "l"(p), "f"(x), "f"(y), "f"(z), "f"(w)
                 : "memory");
}

__global__ void __launch_bounds__(NT) splat_kernel(
    const float* __restrict__ dirs,
    const float* __restrict__ orig,
    const float* __restrict__ nearv,
    const float* __restrict__ farv,
    const float* __restrict__ enc,
    const int*   __restrict__ gidx,
    float* __restrict__ out)
{
    __shared__ float tbl[NSLOT * NT];            // [slot][M], SoA: bank-conflict-free
    __shared__ int   y0s[NT], v0s[NT];
    __shared__ unsigned short list[NT * NSLOT];  // compacted (M, slot) entries
    __shared__ int cnt;

    const int n = blockIdx.x;
    const int M = threadIdx.x;                   // slab = dominant-axis coord

    // ---- per-ray params (broadcast loads) ----
    const float d0 = dirs[n * 3 + 0], d1 = dirs[n * 3 + 1], d2 = dirs[n * 3 + 2];
    const float o0 = orig[n * 3 + 0], o1 = orig[n * 3 + 1], o2 = orig[n * 3 + 2];
    const float nr = nearv[n], fr = farv[n];

    // dominant axis (uniform across block)
    const float ab0 = fabsf(d0), ab1 = fabsf(d1), ab2 = fabsf(d2);
    int a = (ab1 > ab0) ? 1 : 0;
    float am = (ab1 > ab0) ? ab1 : ab0;
    if (ab2 > am) a = 2;

    float oa, ou, ov, da, du_, dv_;
    if (a == 0)      { oa = o0; da = d0; ou = o1; du_ = d1; ov = o2; dv_ = d2; }
    else if (a == 1) { oa = o1; da = d1; ou = o2; du_ = d2; ov = o0; dv_ = d0; }
    else             { oa = o2; da = d2; ou = o0; du_ = d0; ov = o1; dv_ = d1; }

    // line model in voxel coords (approx ok: exactness comes from per-sample tests)
    const float ca = (oa + 1.0f) * 63.5f;
    const float ma = da * 63.5f;
    const float cu = (ou + 1.0f) * 63.5f;
    const float mu = du_ * 63.5f;
    const float cv = (ov + 1.0f) * 63.5f;
    const float mv = dv_ * 63.5f;

    const float tM = ((float)M - ca) / ma;
    const float Yl = cu + mu * tM;
    const float Zl = cv + mv * tM;
    const int y0 = (int)floorf(Yl) - 1;
    const int v0 = (int)floorf(Zl) - 1;
    y0s[M] = y0;
    v0s[M] = v0;
    if (M == 0) cnt = 0;

#pragma unroll
    for (int i = 0; i < NSLOT; i++) tbl[i * NT + M] = 0.0f;
    // no sync needed: each thread touches only its own column until the barrier

    const int b_ = gidx[n];

    // process one sample at depth t: claim this slab's dominant-axis corner(s)
    auto process = [&](float t) {
        const float pa_ = oa + t * da;
        const float va  = (pa_ + 1.0f) * 0.5f * 127.0f;   // same op order as reference
        const float baf = floorf(va);
        const float Mf  = (float)M;
        float wa;
        if (baf == Mf)             wa = 1.0f - (va - baf); // dx=0 corner at ix=M
        else if (baf == Mf - 1.0f) wa = va - baf;          // dx=1 corner at ix=M
        else return;

        const float pu_ = ou + t * du_;
        const float vu  = (pu_ + 1.0f) * 0.5f * 127.0f;
        const float buf = floorf(vu);
        const float fu  = vu - buf;

        const float pv_ = ov + t * dv_;
        const float vv  = (pv_ + 1.0f) * 0.5f * 127.0f;
        const float bvf = floorf(vv);
        const float fv  = vv - bvf;

        const int du0 = (int)buf - y0;
        const int dv0 = (int)bvf - v0;

        if ((unsigned)du0 <= 2u && (unsigned)dv0 <= 2u) {
            const int s00 = du0 * 4 + dv0;
            tbl[(s00)     * NT + M] += wa * (1.0f - fu) * (1.0f - fv);
            tbl[(s00 + 1) * NT + M] += wa * (1.0f - fu) * fv;
            tbl[(s00 + 4) * NT + M] += wa * fu * (1.0f - fv);
            tbl[(s00 + 5) * NT + M] += wa * fu * fv;
        } else {
            // ulp-boundary fallback: direct global reductions (essentially never)
#pragma unroll
            for (int k = 0; k < 4; k++) {
                const int dyu = k >> 1, dyv = k & 1;
                const int iu_ = (int)buf + dyu;
                const int iv_ = (int)bvf + dyv;
                if ((unsigned)iu_ >= 128u || (unsigned)iv_ >= 128u) continue;
                const float w = wa * (dyu ? fu : 1.0f - fu) * (dyv ? fv : 1.0f - fv);
                int ix, iy, iz;
                if (a == 0)      { ix = M;   iy = iu_; iz = iv_; }
                else if (a == 1) { iy = M;   iz = iu_; ix = iv_; }
                else             { iz = M;   ix = iu_; iy = iv_; }
                float* p = out + ((((long long)b_ * GD + iz) * GH + iy) * GW + ix) * GC;
#pragma unroll
                for (int q = 0; q < 4; q++) {
                    const float4 e4 = *reinterpret_cast<const float4*>(enc + n * GC + q * 4);
                    red_add_v4(p + q * 4, w * e4.x, w * e4.y, w * e4.z, w * e4.w);
                }
            }
        }
    };

    // ---- regular samples: only the index range whose v_a is near slab M ----
    {
        const float kstep = (fr - nr) * (1.0f / NUM_SAMPLES);
        const float A_ = ca + ma * nr;       // v_a at s+0.5 = 0
        const float B_ = ma * kstep;         // |B_| >= ~0.4, never 0
        const float r0 = ((float)M - 1.0f - A_) / B_;
        const float r1 = ((float)M + 1.0f - A_) / B_;
        const float smin = fminf(r0, r1) - 0.5f;
        const float smax = fmaxf(r0, r1) - 0.5f;
        int s0 = (int)floorf(fmaxf(smin, -2.0f)) - 1; if (s0 < 0) s0 = 0;
        int s1 = (int)ceilf (fminf(smax, 66.0f)) + 1; if (s1 > NUM_SAMPLES - 1) s1 = NUM_SAMPLES - 1;
        for (int s = s0; s <= s1; s++) {
            const float t = nr + (fr - nr) * (((float)s + 0.5f) * (1.0f / NUM_SAMPLES));
            process(t);
        }
    }

    // ---- disparity samples: test all 8 with a conservative pre-filter ----
    {
        const float inv_far = 1.0f / fr;
#pragma unroll
        for (int j = 1; j <= NUM_SAMPLES_INF; j++) {
            const float jj = (float)j * (1.0f / NUM_SAMPLES_INF);
            const float disp = inv_far + (DISPARITY_AT_INF - inv_far) * jj;
            const float t = 1.0f / disp;
            const float va_ = (oa + t * da + 1.0f) * 0.5f * 127.0f;
            // conservative window; exact claim happens inside process()
            if (va_ >= (float)M - 1.5f && va_ <= (float)M + 1.5f) process(t);
        }
    }

    __syncthreads();

    // ---- compact nonzero, in-bounds vertices ----
#pragma unroll
    for (int idx = 0; idx < NSLOT; idx++) {
        const float w = tbl[idx * NT + M];
        if (w != 0.0f) {
            const int iu_ = y0 + (idx >> 2);
            const int iv_ = v0 + (idx & 3);
            if ((unsigned)iu_ < 128u && (unsigned)iv_ < 128u) {
                const int pos = atomicAdd(&cnt, 1);
                list[pos] = (unsigned short)((M << 4) | idx);
            }
        }
    }
    __syncthreads();

    // ---- flush: 4-lane quads, one 64B red.v4 group per distinct vertex ----
    const int nent = cnt;
    const int c4 = M & 3;
    const int g  = M >> 2;   // 0..31 quad groups
    const float4 e4 = *reinterpret_cast<const float4*>(enc + n * GC + c4 * 4);

    for (int i = g; i < nent; i += NT / 4) {
        const unsigned ent = list[i];
        const int Mm  = (int)(ent >> 4);
        const int idx = (int)(ent & 15u);
        const float w = tbl[idx * NT + Mm];
        const int iu_ = y0s[Mm] + (idx >> 2);
        const int iv_ = v0s[Mm] + (idx & 3);
        int ix, iy, iz;
        if (a == 0)      { ix = Mm;  iy = iu_; iz = iv_; }
        else if (a == 1) { iy = Mm;  iz = iu_; ix = iv_; }
        else             { iz = Mm;  ix = iu_; iy = iv_; }
        float* p = out + ((((long long)b_ * GD + iz) * GH + iy) * GW + ix) * GC + c4 * 4;
        red_add_v4(p, w * e4.x, w * e4.y, w * e4.z, w * e4.w);
    }
}

extern "C" void kernel_launch(void* const* d_in, const int* in_sizes, int n_in,
                              void* d_out, int out_size)
{
    const float* dirs  = (const float*)d_in[0];
    const float* orig  = (const float*)d_in[1];
    const float* nearv = (const float*)d_in[2];
    const float* farv  = (const float*)d_in[3];
    const float* enc   = (const float*)d_in[4];
    const int*   gidx  = (const int*)  d_in[5];
    float* out = (float*)d_out;

    const int N = in_sizes[2];  // near has one element per ray

    cudaMemsetAsync(d_out, 0, (size_t)out_size * sizeof(float));

    splat_kernel<<<N, NT>>>(dirs, orig, nearv, farv, enc, gidx, out);
}